// round 2
// baseline (speedup 1.0000x reference)
#include <cuda_runtime.h>
#include <cstdint>

#define CDIV(a,b) (((a)+(b)-1)/(b))

constexpr int Nn  = 50000;
constexpr int Ed  = 256;
constexpr int Hd  = 512;
constexpr int NEx = 5;
constexpr int GHd = 128;
constexpr int CC  = 768;   // 3*Ed

// ---------------- scratch (static device globals; no allocation) -------------
__device__ float g_concat[(size_t)Nn * CC];          // 153.6 MB
__device__ float g_ghid[(size_t)Nn * GHd];           // 25.6 MB
__device__ int   g_lists[NEx * Nn];                  // routing lists (per-expert segment of Nn)
__device__ float g_gatew[NEx * Nn];                  // gate weight per assignment
__device__ int   g_counts[NEx];
__device__ float g_h1[(size_t)NEx * Nn * Hd];        // expert hidden, 512 MB
__device__ float g_nf[(size_t)Nn * Hd];              // node_feats (h^0)
__device__ float g_hw[(size_t)Nn * Hd];              // h @ Wnbr
__device__ float g_msg[(size_t)Nn * Hd];             // segment sum
__device__ float g_hl[(size_t)Nn * Hd];              // h after layer 0

// ---------------- helpers ----------------------------------------------------
__device__ __forceinline__ float gelu_f(float x) {
    float t = tanhf(0.7978845608028654f * (x + 0.044715f * x * x * x));
    return 0.5f * x * (1.0f + t);
}

// ---------------- concat [text|tabular|structured] ---------------------------
__global__ void k_concat(const float* __restrict__ text,
                         const float* __restrict__ tab,
                         const float* __restrict__ str) {
    int i = blockIdx.x * blockDim.x + threadIdx.x;       // float4 index
    const int per_row = CC / 4;                          // 192
    if (i >= Nn * per_row) return;
    int n = i / per_row, c = i % per_row;
    const float4* src;
    int cc;
    if (c < 64)       { src = (const float4*)text; cc = c; }
    else if (c < 128) { src = (const float4*)tab;  cc = c - 64; }
    else              { src = (const float4*)str;  cc = c - 128; }
    ((float4*)g_concat)[i] = src[(size_t)n * 64 + cc];
}

// ---------------- SGEMM core: 128x128 tile, BK=8, 256 thr, 8x8/thread --------
template<bool GATHER>
__device__ __forceinline__ void gemm_compute(
    const float* __restrict__ A, const float* __restrict__ B,
    const int* __restrict__ rowlist, int M, int K, int ldb,
    float (&acc)[8][8])
{
    __shared__ float As[8][128];
    __shared__ float Bs[8][128];

    const int tid = threadIdx.x;
    const int tx = tid & 15, ty = tid >> 4;
    const int row0 = blockIdx.y * 128;
    const int col0 = blockIdx.x * 128;
    const int lr  = tid >> 1;
    const int lk  = (tid & 1) << 2;
    const int lbk = tid >> 5;
    const int lbn = (tid & 31) << 2;

    const bool avalid = (row0 + lr) < M;
    int arow = row0 + lr;
    if (GATHER) {
        arow = avalid ? rowlist[arow] : 0;
        arow = (arow >= 0 && arow < Nn) ? arow : 0;   // defensive
    } else if (!avalid) arow = 0;

    const float* Ap = A + (size_t)arow * K + lk;
    const float* Bp = B + (size_t)lbk * ldb + col0 + lbn;

    float4 av = avalid ? *(const float4*)Ap : make_float4(0.f, 0.f, 0.f, 0.f);
    float4 bv = *(const float4*)Bp;

    for (int k0 = 0; k0 < K; k0 += 8) {
        As[lk + 0][lr] = av.x; As[lk + 1][lr] = av.y;
        As[lk + 2][lr] = av.z; As[lk + 3][lr] = av.w;
        *(float4*)&Bs[lbk][lbn] = bv;
        __syncthreads();
        if (k0 + 8 < K) {      // prefetch next tile while computing this one
            Ap += 8; Bp += (size_t)8 * ldb;
            av = avalid ? *(const float4*)Ap : make_float4(0.f, 0.f, 0.f, 0.f);
            bv = *(const float4*)Bp;
        }
        #pragma unroll
        for (int k = 0; k < 8; k++) {
            float a[8], b[8];
            *(float4*)(a)     = *(const float4*)&As[k][ty * 8];
            *(float4*)(a + 4) = *(const float4*)&As[k][ty * 8 + 4];
            *(float4*)(b)     = *(const float4*)&Bs[k][tx * 8];
            *(float4*)(b + 4) = *(const float4*)&Bs[k][tx * 8 + 4];
            #pragma unroll
            for (int i = 0; i < 8; i++)
                #pragma unroll
                for (int j = 0; j < 8; j++)
                    acc[i][j] = fmaf(a[i], b[j], acc[i][j]);
        }
        __syncthreads();
    }
}

// ---------------- generic GEMM (dense rows) with optional bias / add / relu --
// ACT: 0 = none, 1 = relu
template<int ACT, bool ADDMAT>
__global__ void __launch_bounds__(256, 2) k_gemm(
    const float* __restrict__ A, const float* __restrict__ B,
    const float* __restrict__ bias, const float* __restrict__ addmat,
    float* __restrict__ C, int M, int K, int NC)
{
    float acc[8][8];
    #pragma unroll
    for (int i = 0; i < 8; i++)
        #pragma unroll
        for (int j = 0; j < 8; j++) acc[i][j] = 0.f;

    gemm_compute<false>(A, B, nullptr, M, K, NC, acc);

    const int tid = threadIdx.x, tx = tid & 15, ty = tid >> 4;
    const int row0 = blockIdx.y * 128 + ty * 8;
    const int col0 = blockIdx.x * 128 + tx * 8;
    #pragma unroll
    for (int i = 0; i < 8; i++) {
        int r = row0 + i;
        if (r >= M) continue;
        #pragma unroll
        for (int jj = 0; jj < 8; jj += 4) {
            int c = col0 + jj;
            float4 v = *(float4*)&acc[i][jj];
            if (bias) {
                v.x += bias[c]; v.y += bias[c + 1]; v.z += bias[c + 2]; v.w += bias[c + 3];
            }
            if (ADDMAT) {
                float4 m = *(const float4*)&addmat[(size_t)r * NC + c];
                v.x += m.x; v.y += m.y; v.z += m.z; v.w += m.w;
            }
            if (ACT == 1) {
                v.x = fmaxf(v.x, 0.f); v.y = fmaxf(v.y, 0.f);
                v.z = fmaxf(v.z, 0.f); v.w = fmaxf(v.w, 0.f);
            }
            *(float4*)&C[(size_t)r * NC + c] = v;
        }
    }
}

// ---------------- gating head: logits -> softmax -> top2 -> routing lists ----
// block = 1024 threads = 32 warps = 32 nodes; smem-aggregated list append
__global__ void k_gate(const float* __restrict__ Wg2, const float* __restrict__ bg2) {
    __shared__ int   scnt[NEx], sbase[NEx];
    __shared__ int   se[64];
    __shared__ int   snode[64];
    __shared__ int   spos[64];
    __shared__ float sg[64];

    const int tid = threadIdx.x;
    if (tid < NEx) scnt[tid] = 0;
    __syncthreads();

    const int warp = tid >> 5, lane = tid & 31;
    const int node = blockIdx.x * 32 + warp;

    if (node < Nn) {
        const float* gr = g_ghid + (size_t)node * GHd;
        float v0 = gr[lane], v1 = gr[lane + 32], v2 = gr[lane + 64], v3 = gr[lane + 96];
        float l[NEx];
        #pragma unroll
        for (int e = 0; e < NEx; e++) {
            float p = v0 * Wg2[lane * NEx + e]
                    + v1 * Wg2[(lane + 32) * NEx + e]
                    + v2 * Wg2[(lane + 64) * NEx + e]
                    + v3 * Wg2[(lane + 96) * NEx + e];
            #pragma unroll
            for (int off = 16; off > 0; off >>= 1)
                p += __shfl_xor_sync(0xffffffffu, p, off);
            l[e] = p;
        }
        if (lane == 0) {
            #pragma unroll
            for (int e = 0; e < NEx; e++) l[e] += bg2[e];
            int e0 = 0;
            #pragma unroll
            for (int e = 1; e < NEx; e++) if (l[e] > l[e0]) e0 = e;
            int e1 = -1;
            #pragma unroll
            for (int e = 0; e < NEx; e++)
                if (e != e0 && (e1 < 0 || l[e] > l[e1])) e1 = e;
            float gate0 = 1.f / (1.f + expf(l[e1] - l[e0]));
            float gate1 = 1.f - gate0;
            int s0 = warp * 2, s1 = warp * 2 + 1;
            se[s0] = e0; snode[s0] = node; sg[s0] = gate0;
            spos[s0] = atomicAdd(&scnt[e0], 1);
            se[s1] = e1; snode[s1] = node; sg[s1] = gate1;
            spos[s1] = atomicAdd(&scnt[e1], 1);
        }
    } else if (lane == 0) {
        se[warp * 2] = -1; se[warp * 2 + 1] = -1;
    }
    __syncthreads();
    if (tid < NEx) sbase[tid] = atomicAdd(&g_counts[tid], scnt[tid]);
    __syncthreads();
    if (tid < 64 && se[tid] >= 0) {
        int e = se[tid];
        int p = sbase[e] + spos[tid];
        if (p >= 0 && p < Nn) {
            g_lists[e * Nn + p] = snode[tid];
            g_gatew[e * Nn + p] = sg[tid];
        }
    }
}

// ---------------- expert layer 1: gathered rows, gelu ------------------------
__global__ void __launch_bounds__(256, 2) k_expert1(
    const float* __restrict__ text, const float* __restrict__ tab,
    const float* __restrict__ str,
    const float* __restrict__ We1, const float* __restrict__ be1)
{
    const int e = blockIdx.z;
    int M = g_counts[e];
    M = (M < Nn) ? M : Nn;
    if ((int)(blockIdx.y * 128) >= M) return;

    const float* xs[3] = { text, tab, str };
    const int map[NEx] = { 1, 2, 0, 0, 2 };   // xin = [tabular, structured, text, text, structured]
    const float* A = xs[map[e]];

    float acc[8][8];
    #pragma unroll
    for (int i = 0; i < 8; i++)
        #pragma unroll
        for (int j = 0; j < 8; j++) acc[i][j] = 0.f;

    gemm_compute<true>(A, We1 + (size_t)e * Ed * Hd, g_lists + e * Nn, M, Ed, Hd, acc);

    const float* bias = be1 + e * Hd;
    float* C = g_h1 + (size_t)e * Nn * Hd;
    const int tid = threadIdx.x, tx = tid & 15, ty = tid >> 4;
    const int row0 = blockIdx.y * 128 + ty * 8;
    const int col0 = blockIdx.x * 128 + tx * 8;
    #pragma unroll
    for (int i = 0; i < 8; i++) {
        int r = row0 + i;
        if (r >= M) continue;
        #pragma unroll
        for (int jj = 0; jj < 8; jj += 4) {
            int c = col0 + jj;
            float4 v;
            v.x = gelu_f(acc[i][jj + 0] + bias[c + 0]);
            v.y = gelu_f(acc[i][jj + 1] + bias[c + 1]);
            v.z = gelu_f(acc[i][jj + 2] + bias[c + 2]);
            v.w = gelu_f(acc[i][jj + 3] + bias[c + 3]);
            *(float4*)&C[(size_t)r * Hd + c] = v;
        }
    }
}

// ---------------- expert layer 2: scatter gate*out into node_feats -----------
__global__ void __launch_bounds__(256, 2) k_expert2(
    const float* __restrict__ We2, const float* __restrict__ be2)
{
    const int e = blockIdx.z;
    int M = g_counts[e];
    M = (M < Nn) ? M : Nn;
    if ((int)(blockIdx.y * 128) >= M) return;

    const float* A = g_h1 + (size_t)e * Nn * Hd;

    float acc[8][8];
    #pragma unroll
    for (int i = 0; i < 8; i++)
        #pragma unroll
        for (int j = 0; j < 8; j++) acc[i][j] = 0.f;

    gemm_compute<false>(A, We2 + (size_t)e * Hd * Hd, nullptr, M, Hd, Hd, acc);

    const float* bias = be2 + e * Hd;
    const int*   lst  = g_lists + e * Nn;
    const float* gw   = g_gatew + e * Nn;
    const int tid = threadIdx.x, tx = tid & 15, ty = tid >> 4;
    const int row0 = blockIdx.y * 128 + ty * 8;
    const int col0 = blockIdx.x * 128 + tx * 8;
    #pragma unroll
    for (int i = 0; i < 8; i++) {
        int r = row0 + i;
        if (r >= M) continue;
        int node = lst[r];
        if (node < 0 || node >= Nn) continue;   // defensive
        float g = gw[r];
        float* dst = g_nf + (size_t)node * Hd;
        #pragma unroll
        for (int jj = 0; jj < 8; jj += 4) {
            int c = col0 + jj;
            float4 v;
            v.x = g * (acc[i][jj + 0] + bias[c + 0]);
            v.y = g * (acc[i][jj + 1] + bias[c + 1]);
            v.z = g * (acc[i][jj + 2] + bias[c + 2]);
            v.w = g * (acc[i][jj + 3] + bias[c + 3]);
            atomicAdd((float4*)(dst + c), v);
        }
    }
}

// ---------------- edge segment-sum: msg[dst] += hw[src] ----------------------
// edge_index is int32 (JAX x64 disabled downcasts int64 -> int32)
__global__ void k_scatter(const int* __restrict__ ei, int nedges,
                          const float* __restrict__ hw, float* __restrict__ msg)
{
    int idx = blockIdx.x * blockDim.x + threadIdx.x;
    int eidx = idx >> 7;           // 128 threads per edge
    int t = idx & 127;
    if (eidx >= nedges) return;
    int s = ei[eidx];
    int d = ei[nedges + eidx];
    if ((unsigned)s >= (unsigned)Nn || (unsigned)d >= (unsigned)Nn) return;  // defensive
    float4 v = ((const float4*)(hw + (size_t)s * Hd))[t];
    atomicAdd((float4*)(msg + (size_t)d * Hd + (size_t)t * 4), v);
}

// ---------------- launch -----------------------------------------------------
extern "C" void kernel_launch(void* const* d_in, const int* in_sizes, int n_in,
                              void* d_out, int out_size)
{
    const float* text = (const float*)d_in[0];
    const float* tab  = (const float*)d_in[1];
    const float* str  = (const float*)d_in[2];
    const int*   ei   = (const int*)d_in[3];     // int32 edge index
    const float* Wg1  = (const float*)d_in[4];
    const float* bg1  = (const float*)d_in[5];
    const float* Wg2  = (const float*)d_in[6];
    const float* bg2  = (const float*)d_in[7];
    const float* We1  = (const float*)d_in[8];
    const float* be1  = (const float*)d_in[9];
    const float* We2  = (const float*)d_in[10];
    const float* be2  = (const float*)d_in[11];
    const float* Wself = (const float*)d_in[12];
    const float* Wnbr  = (const float*)d_in[13];
    float* out = (float*)d_out;
    const int nedges = in_sizes[3] / 2;

    void *pcnt, *pconcat, *pghid, *pnf, *phw, *pmsg, *phl;
    cudaGetSymbolAddress(&pcnt,    g_counts);
    cudaGetSymbolAddress(&pconcat, g_concat);
    cudaGetSymbolAddress(&pghid,   g_ghid);
    cudaGetSymbolAddress(&pnf,     g_nf);
    cudaGetSymbolAddress(&phw,     g_hw);
    cudaGetSymbolAddress(&pmsg,    g_msg);
    cudaGetSymbolAddress(&phl,     g_hl);

    cudaMemsetAsync(pcnt, 0, sizeof(int) * NEx);
    cudaMemsetAsync(pnf,  0, sizeof(float) * (size_t)Nn * Hd);

    // 1) concat inputs
    k_concat<<<CDIV(Nn * (CC / 4), 256), 256>>>(text, tab, str);

    // 2) gating hidden: relu(concat @ Wg1 + bg1)
    k_gemm<1, false><<<dim3(GHd / 128, CDIV(Nn, 128)), 256>>>(
        (const float*)pconcat, Wg1, bg1, nullptr, (float*)pghid, Nn, CC, GHd);

    // 3) gating head: softmax top-2, build routing lists
    k_gate<<<CDIV(Nn, 32), 1024>>>(Wg2, bg2);

    // 4) expert MLP layer 1 (gathered, gelu), all 5 experts in one launch
    k_expert1<<<dim3(Hd / 128, CDIV(Nn, 128), NEx), 256>>>(text, tab, str, We1, be1);

    // 5) expert MLP layer 2, scatter gate*out into node_feats
    k_expert2<<<dim3(Hd / 128, CDIV(Nn, 128), NEx), 256>>>(We2, be2);

    // ---- GNN layer 0 ----
    k_gemm<0, false><<<dim3(Hd / 128, CDIV(Nn, 128)), 256>>>(
        (const float*)pnf, Wnbr, nullptr, nullptr, (float*)phw, Nn, Hd, Hd);
    cudaMemsetAsync(pmsg, 0, sizeof(float) * (size_t)Nn * Hd);
    k_scatter<<<CDIV(nedges * 128, 256), 256>>>(ei, nedges, (const float*)phw, (float*)pmsg);
    k_gemm<1, true><<<dim3(Hd / 128, CDIV(Nn, 128)), 256>>>(
        (const float*)pnf, Wself, nullptr, (const float*)pmsg, (float*)phl, Nn, Hd, Hd);

    // ---- GNN layer 1 ----
    k_gemm<0, false><<<dim3(Hd / 128, CDIV(Nn, 128)), 256>>>(
        (const float*)phl, Wnbr + (size_t)Hd * Hd, nullptr, nullptr, (float*)phw, Nn, Hd, Hd);
    cudaMemsetAsync(pmsg, 0, sizeof(float) * (size_t)Nn * Hd);
    k_scatter<<<CDIV(nedges * 128, 256), 256>>>(ei, nedges, (const float*)phw, (float*)pmsg);
    k_gemm<1, true><<<dim3(Hd / 128, CDIV(Nn, 128)), 256>>>(
        (const float*)phl, Wself + (size_t)Hd * Hd, nullptr, (const float*)pmsg, out, Nn, Hd, Hd);
}